// round 8
// baseline (speedup 1.0000x reference)
#include <cuda_runtime.h>

#define H 512
#define LSEQ 1024
#define NROWS 4096
#define NST 64

typedef unsigned long long u64;

// ---- packed f32x2 (FFMA2) helpers ----
__device__ __forceinline__ u64 pack2(float x, float y) {
    u64 r; asm("mov.b64 %0,{%1,%2};" : "=l"(r) : "f"(x), "f"(y)); return r;
}
__device__ __forceinline__ u64 dup2(float x) { return pack2(x, x); }
__device__ __forceinline__ void unpack2(u64 v, float& x, float& y) {
    asm("mov.b64 {%0,%1},%2;" : "=f"(x), "=f"(y) : "l"(v));
}
__device__ __forceinline__ void fma2(u64& d, u64 a, u64 b) {
    asm("fma.rn.f32x2 %0,%1,%2,%0;" : "+l"(d) : "l"(a), "l"(b));
}

// ---- complex helpers ----
__device__ __forceinline__ float2 cmul(float2 a, float2 b) {
    return make_float2(a.x*b.x - a.y*b.y, a.x*b.y + a.y*b.x);
}
__device__ __forceinline__ float2 cadd(float2 a, float2 b) { return make_float2(a.x+b.x, a.y+b.y); }
__device__ __forceinline__ float2 csub(float2 a, float2 b) { return make_float2(a.x-b.x, a.y-b.y); }
__device__ __forceinline__ float2 cscale(float2 a, float s) { return make_float2(a.x*s, a.y*s); }
__device__ __forceinline__ float2 cinv(float2 d) {
    float inv = 1.f / (d.x*d.x + d.y*d.y);
    return make_float2(d.x*inv, -d.y*inv);
}

// ---- scratch: device globals ----
__device__ float  g_xn[NROWS * H];
__device__ float  g_yg[NROWS * H];
__device__ float  g_part[8][NROWS * H];
__device__ float  g_K[LSEQ];

// ================= LayerNorm =================
__global__ void k_ln(const float* __restrict__ x, const float* __restrict__ w,
                     const float* __restrict__ bi) {
    int row = blockIdx.x;
    int t = threadIdx.x;  // 128 threads, float4 each
    float4 v = ((const float4*)(x + (size_t)row * H))[t];
    float s  = v.x + v.y + v.z + v.w;
    float ss = v.x*v.x + v.y*v.y + v.z*v.z + v.w*v.w;
    __shared__ float rs[4], rss[4];
#pragma unroll
    for (int o = 16; o > 0; o >>= 1) {
        s  += __shfl_down_sync(0xffffffffu, s, o);
        ss += __shfl_down_sync(0xffffffffu, ss, o);
    }
    if ((t & 31) == 0) { rs[t >> 5] = s; rss[t >> 5] = ss; }
    __syncthreads();
    float sum = rs[0] + rs[1] + rs[2] + rs[3];
    float sq  = rss[0] + rss[1] + rss[2] + rss[3];
    float mu = sum * (1.f / H);
    float var = sq * (1.f / H) - mu * mu;
    float rstd = rsqrtf(var + 1e-5f);
    float4 wv = ((const float4*)w)[t];
    float4 bv = ((const float4*)bi)[t];
    float4 o;
    o.x = (v.x - mu) * rstd * wv.x + bv.x;
    o.y = (v.y - mu) * rstd * wv.y + bv.y;
    o.z = (v.z - mu) * rstd * wv.z + bv.z;
    o.w = (v.w - mu) * rstd * wv.w + bv.w;
    ((float4*)(g_xn + (size_t)row * H))[t] = o;
}

// ================= Fused K pipeline (single block, 1024 threads) =================
// Ab = D + u v^T (diag + rank-1).  Structured squaring with rank doubling:
//   (D + U V^T)^2 = D^2 + [DU, U] [V, DV + V (V^T U)^T]^T
// s_k doubling uses each power right after it's formed; r_m chain uses Ab^64.
// Shared layout (float2 units):
//   U[64*64], V[64*64], S[64*64], Mb[32*32], R[16*64],
//   Dv[64], w64[64], Rc[64], Rn[64], red[2]
#define KP_SMEM_F2 (4096*3 + 1024 + 1024 + 64*4 + 2)

__global__ void __launch_bounds__(1024, 1) k_kpipe(
    const float* lre, const float* lim, const float* pre, const float* pim,
    const float* bre, const float* bim, const float* logstep,
    const float* cre, const float* cim) {
    extern __shared__ float2 sm[];
    float2* U   = sm;
    float2* V   = U + 4096;
    float2* S   = V + 4096;
    float2* Mb  = S + 4096;      // also used as W in apply phase
    float2* R   = Mb + 1024;
    float2* Dv  = R + 1024;
    float2* w64 = Dv + 64;
    float2* Rc  = w64 + 64;
    float2* Rn  = Rc + 64;
    float2* red = Rn + 64;

    int tid = threadIdx.x;
    const float2 zero = make_float2(0.f, 0.f);

    // ---- setup: g, u, v, Bb (threads 0..63 own lane i; syncs uniform) ----
    {
        float dt = expf(logstep[0]);
        float w0 = 2.f / dt;
        float2 lam = zero, p = zero, bb = zero, Dl = zero, d0 = zero;
        float2 sig_part = zero;
        if (tid < NST) {
            lam = make_float2(lre[tid], lim[tid]);
            p   = make_float2(pre[tid], pim[tid]);
            bb  = make_float2(bre[tid], bim[tid]);
            Dl  = cinv(make_float2(w0 - lam.x, -lam.y));
            d0  = make_float2(w0 + lam.x, lam.y);
            float pn2 = p.x*p.x + p.y*p.y;
            sig_part = cscale(Dl, pn2);
        }
#pragma unroll
        for (int o = 16; o > 0; o >>= 1) {
            sig_part.x += __shfl_down_sync(0xffffffffu, sig_part.x, o);
            sig_part.y += __shfl_down_sync(0xffffffffu, sig_part.y, o);
        }
        if (tid < NST && (tid & 31) == 0) red[tid >> 5] = sig_part;
        __syncthreads();
        float2 sig = cadd(red[0], red[1]);
        __syncthreads();

        float2 Db = zero, tau_part = zero, p_l = p;
        if (tid < NST) {
            Db = cmul(Dl, bb);
            tau_part = cmul(make_float2(p_l.x, -p_l.y), Db);
        }
#pragma unroll
        for (int o = 16; o > 0; o >>= 1) {
            tau_part.x += __shfl_down_sync(0xffffffffu, tau_part.x, o);
            tau_part.y += __shfl_down_sync(0xffffffffu, tau_part.y, o);
        }
        if (tid < NST && (tid & 31) == 0) red[tid >> 5] = tau_part;
        __syncthreads();
        float2 tau = cadd(red[0], red[1]);

        if (tid < NST) {
            float2 alpha = cinv(make_float2(1.f + sig.x, sig.y));
            float2 uu = cmul(Dl, p_l);
            float2 gg = cmul(Dl, d0);
            float2 as = cmul(alpha, sig);
            float2 coef = csub(make_float2(as.x - 1.f, as.y), cmul(alpha, gg));
            float2 vv = cmul(make_float2(p_l.x, -p_l.y), coef);
            float2 Bv = cscale(csub(Db, cmul(cmul(alpha, tau), uu)), 2.f);
            Dv[tid] = gg;
            U[tid * 64 + 0] = uu;
            V[tid * 64 + 0] = vv;
            S[0 * 64 + tid] = Bv;
        }
        __syncthreads();
    }

    // ---- interleaved: apply Ab^(2^j) to s_0..s_{2^j-1}, then square ----
    for (int j = 0; j < 6; j++) {
        int r = 1 << j;
        // phase1: W[k][a] = sum_n V[n][a] * S[k][n]   (k<2^j, a<r)
        for (int id = tid; id < (r << j); id += 1024) {
            int k = id >> j, a = id & (r - 1);
            float2 acc = zero;
#pragma unroll 8
            for (int n = 0; n < NST; n++) acc = cadd(acc, cmul(V[n * 64 + a], S[k * 64 + n]));
            Mb[k * 32 + a] = acc;
        }
        __syncthreads();
        // phase2: S[k+r][n] = D[n]*S[k][n] + sum_a U[n][a]*W[k][a]
        for (int id = tid; id < (NST << j); id += 1024) {
            int k = id >> 6, n = id & 63;
            float2 acc = cmul(Dv[n], S[k * 64 + n]);
            for (int a = 0; a < r; a++) acc = cadd(acc, cmul(U[n * 64 + a], Mb[k * 32 + a]));
            S[(k + r) * 64 + n] = acc;
        }
        __syncthreads();
        // square step 1: M[a][b] = sum_n V[n][a]*U[n][b]
        for (int id = tid; id < r * r; id += 1024) {
            int a = id >> j, b = id & (r - 1);
            float2 acc = zero;
#pragma unroll 8
            for (int n = 0; n < NST; n++) acc = cadd(acc, cmul(V[n * 64 + a], U[n * 64 + b]));
            Mb[a * 32 + b] = acc;
        }
        __syncthreads();
        // square step 2: U <- [DU, U], V <- [V, DV + V M^T]
        for (int id = tid; id < NST * r; id += 1024) {
            int n = id >> j, a = id & (r - 1);
            float2 tu = U[n * 64 + a];
            U[n * 64 + r + a] = tu;
            U[n * 64 + a] = cmul(Dv[n], tu);
            float2 av = cmul(Dv[n], V[n * 64 + a]);
            for (int b = 0; b < r; b++) av = cadd(av, cmul(V[n * 64 + b], Mb[a * 32 + b]));
            V[n * 64 + r + a] = av;
        }
        __syncthreads();
        if (tid < NST) Dv[tid] = cmul(Dv[tid], Dv[tid]);
        __syncthreads();
    }
    // now Ab^64 = Dv + U V^T (rank 64)

    // ---- r_m chain: r_{m+1} = D o r + V (U^T r) ----
    if (tid < NST) Rc[tid] = make_float2(cre[tid], cim[tid]);
    __syncthreads();
    for (int m = 0; m < 16; m++) {
        if (tid < NST) R[m * 64 + tid] = Rc[tid];
        {
            int a = tid >> 4, q = tid & 15;
            float2 acc = zero;
#pragma unroll
            for (int i2 = 0; i2 < 4; i2++) {
                int n = q * 4 + i2;
                acc = cadd(acc, cmul(U[n * 64 + a], Rc[n]));
            }
#pragma unroll
            for (int o = 8; o > 0; o >>= 1) {
                acc.x += __shfl_down_sync(0xffffffffu, acc.x, o, 16);
                acc.y += __shfl_down_sync(0xffffffffu, acc.y, o, 16);
            }
            if (q == 0) w64[a] = acc;
        }
        __syncthreads();
        {
            int n = tid >> 4, q = tid & 15;
            float2 acc = zero;
#pragma unroll
            for (int i2 = 0; i2 < 4; i2++) {
                int a = q * 4 + i2;
                acc = cadd(acc, cmul(V[n * 64 + a], w64[a]));
            }
#pragma unroll
            for (int o = 8; o > 0; o >>= 1) {
                acc.x += __shfl_down_sync(0xffffffffu, acc.x, o, 16);
                acc.y += __shfl_down_sync(0xffffffffu, acc.y, o, 16);
            }
            if (q == 0) Rn[n] = cadd(cmul(Dv[n], Rc[n]), acc);
        }
        __syncthreads();
        if (tid < NST) Rc[tid] = Rn[tid];
        __syncthreads();
    }

    // ---- K[64m+k] = Re( sum_n R[m][n] * S[k][n] ) ----
    {
        int m = tid >> 6, k = tid & 63;
        float acc = 0.f;
#pragma unroll 8
        for (int n = 0; n < NST; n++) {
            float2 a = R[m * 64 + n], s = S[k * 64 + n];
            acc += a.x * s.x - a.y * s.y;
        }
        g_K[m * 64 + k] = acc;
    }
}

// ================= causal Toeplitz conv, split-buffer partials =================
// grid 576 = 4 b x 4 hT x 36 triangular (tT,sT); 128x128x128 tile per block
__global__ void __launch_bounds__(256, 2) k_conv() {
    int idx = blockIdx.x;
    int b = idx / 144;
    int rem = idx - b * 144;
    int hT = rem / 36;
    int pr = rem - hT * 36;
    int tT = 0;
    while ((tT + 1) * (tT + 2) / 2 <= pr) tT++;
    int sT = pr - tT * (tT + 1) / 2;
    int t0 = tT * 128, s0 = sT * 128, h0 = hT * 128;
    int D0 = t0 - s0;

    __shared__ float Ks[264];
    __shared__ float Xs[32][128];
    const float* X = g_xn + (size_t)(b * LSEQ) * H;
    int tid = threadIdx.x;
    for (int jj = tid; jj < 264; jj += 256) {
        int d = D0 + jj - 131;
        Ks[jj] = (d >= 0 && d < LSEQ) ? g_K[d] : 0.f;
    }
    int ty = tid >> 4, tx = tid & 15;
    u64 acc[8][4];
#pragma unroll
    for (int r = 0; r < 8; r++)
#pragma unroll
        for (int c = 0; c < 4; c++) acc[r][c] = 0ull;

    const float* KSp = Ks + 131 + ty * 8;

    for (int ch = 0; ch < 4; ch++) {
        __syncthreads();
        {
            int rr = tid >> 5;
            int cc = (tid & 31) * 4;
            const float* src = X + (size_t)(s0 + ch * 32 + rr) * H + h0 + cc;
#pragma unroll
            for (int k2 = 0; k2 < 4; k2++)
                *(float4*)&Xs[rr + k2 * 8][cc] = *(const float4*)(src + (size_t)(k2 * 8) * H);
        }
        __syncthreads();
        int base = -ch * 32;
        u64 a2[8];
#pragma unroll
        for (int r = 0; r < 8; r++) a2[r] = dup2(KSp[base + r]);
#pragma unroll
        for (int sl = 0; sl < 32; sl++) {
            u64 xv[4];
#pragma unroll
            for (int c = 0; c < 4; c++) xv[c] = *(const u64*)&Xs[sl][tx * 2 + c * 32];
#pragma unroll
            for (int r = 0; r < 8; r++)
#pragma unroll
                for (int c = 0; c < 4; c++) fma2(acc[r][c], a2[r], xv[c]);
#pragma unroll
            for (int r = 7; r > 0; r--) a2[r] = a2[r - 1];
            a2[0] = dup2(KSp[base - sl - 1]);
        }
    }
    float* P = g_part[sT] + ((size_t)(b * LSEQ) + t0) * H + h0;
#pragma unroll
    for (int r = 0; r < 8; r++) {
        float* Pr = P + (size_t)(ty * 8 + r) * H + tx * 2;
#pragma unroll
        for (int c = 0; c < 4; c++) {
            float va, vb; unpack2(acc[r][c], va, vb);
            *(float2*)(Pr + c * 32) = make_float2(va, vb);
        }
    }
}

// ================= split reduce + d*xn + GELU =================
__global__ void k_gelu(const float* __restrict__ dscale) {
    int idx = blockIdx.x * 256 + threadIdx.x;
    int row = idx >> 7, c4 = idx & 127;
    int t = row & (LSEQ - 1);
    int tT = t >> 7;
    size_t off = (size_t)row * H + c4 * 4;
    float4 s = make_float4(0.f, 0.f, 0.f, 0.f);
    for (int j = 0; j <= tT; j++) {
        float4 p = *(const float4*)(g_part[j] + off);
        s.x += p.x; s.y += p.y; s.z += p.z; s.w += p.w;
    }
    float dv = dscale[0];
    float4 xn = *(const float4*)(g_xn + off);
    float y0 = s.x + dv * xn.x, y1 = s.y + dv * xn.y;
    float y2 = s.z + dv * xn.z, y3 = s.w + dv * xn.w;
    float4 o;
    float z;
    z = 0.7978845608f * (y0 + 0.044715f * y0 * y0 * y0); o.x = y0 / (1.f + __expf(-2.f * z));
    z = 0.7978845608f * (y1 + 0.044715f * y1 * y1 * y1); o.y = y1 / (1.f + __expf(-2.f * z));
    z = 0.7978845608f * (y2 + 0.044715f * y2 * y2 * y2); o.z = y2 / (1.f + __expf(-2.f * z));
    z = 0.7978845608f * (y3 + 0.044715f * y3 * y3 * y3); o.w = y3 / (1.f + __expf(-2.f * z));
    *(float4*)(g_yg + off) = o;
}

// ================= fused dual GEMM + sigmoid gate + residual =================
__global__ void __launch_bounds__(256, 2) k_gemm(
    const float* __restrict__ W1, const float* __restrict__ W2,
    const float* __restrict__ b1, const float* __restrict__ b2,
    const float* __restrict__ skip, float* __restrict__ out) {
    __shared__ float As[32][132];
    __shared__ float Bs[32][132];
    int r0 = blockIdx.x * 128, o0 = blockIdx.y * 64;
    int tid = threadIdx.x, ty = tid >> 4, tx = tid & 15;
    int rr = tid & 127, half = tid >> 7;
    u64 acc[8][4];
#pragma unroll
    for (int r = 0; r < 8; r++)
#pragma unroll
        for (int j = 0; j < 4; j++) acc[r][j] = 0ull;
    const float* Bsrc = (rr < 64) ? (W1 + (size_t)(o0 + rr) * H)
                                  : (W2 + (size_t)(o0 + rr - 64) * H);
    const float* Asrc = g_yg + (size_t)(r0 + rr) * H;

    for (int kc = 0; kc < 16; kc++) {
        __syncthreads();
        int kb = kc * 32 + half * 16;
#pragma unroll
        for (int q = 0; q < 4; q++) {
            float4 av = *(const float4*)(Asrc + kb + q * 4);
            int kk = half * 16 + q * 4;
            As[kk + 0][rr] = av.x; As[kk + 1][rr] = av.y;
            As[kk + 2][rr] = av.z; As[kk + 3][rr] = av.w;
            float4 bv = *(const float4*)(Bsrc + kb + q * 4);
            Bs[kk + 0][rr] = bv.x; Bs[kk + 1][rr] = bv.y;
            Bs[kk + 2][rr] = bv.z; Bs[kk + 3][rr] = bv.w;
        }
        __syncthreads();
#pragma unroll
        for (int kk = 0; kk < 32; kk++) {
            float4 a0 = *(const float4*)&As[kk][ty * 8];
            float4 a1 = *(const float4*)&As[kk][ty * 8 + 4];
            u64 bb[4];
#pragma unroll
            for (int j = 0; j < 4; j++) bb[j] = *(const u64*)&Bs[kk][tx * 2 + j * 32];
            u64 ad[8] = { dup2(a0.x), dup2(a0.y), dup2(a0.z), dup2(a0.w),
                          dup2(a1.x), dup2(a1.y), dup2(a1.z), dup2(a1.w) };
#pragma unroll
            for (int r = 0; r < 8; r++)
#pragma unroll
                for (int j = 0; j < 4; j++) fma2(acc[r][j], ad[r], bb[j]);
        }
    }
#pragma unroll
    for (int r = 0; r < 8; r++) {
        int row = r0 + ty * 8 + r;
        const float* sk = skip + (size_t)row * H;
        float* op = out + (size_t)row * H;
#pragma unroll
        for (int j = 0; j < 2; j++) {
            int o = o0 + tx * 2 + j * 32;
            float p1a, p1b, p2a, p2b;
            unpack2(acc[r][j], p1a, p1b);
            unpack2(acc[r][j + 2], p2a, p2b);
            float v1 = p1a + b1[o], v2 = p1b + b1[o + 1];
            float g1 = p2a + b2[o], g2 = p2b + b2[o + 1];
            float o1 = sk[o]     + v1 / (1.f + __expf(-g1));
            float o2 = sk[o + 1] + v2 / (1.f + __expf(-g2));
            *(float2*)(op + o) = make_float2(o1, o2);
        }
    }
}

extern "C" void kernel_launch(void* const* d_in, const int* in_sizes, int n_in,
                              void* d_out, int out_size) {
    const float* x   = (const float*)d_in[0];
    const float* nw  = (const float*)d_in[1];
    const float* nb  = (const float*)d_in[2];
    const float* lre = (const float*)d_in[3];
    const float* lim = (const float*)d_in[4];
    const float* pre = (const float*)d_in[5];
    const float* pim = (const float*)d_in[6];
    const float* bre = (const float*)d_in[7];
    const float* bim = (const float*)d_in[8];
    const float* cre = (const float*)d_in[9];
    const float* cim = (const float*)d_in[10];
    const float* dd  = (const float*)d_in[11];
    const float* ls  = (const float*)d_in[12];
    const float* W1  = (const float*)d_in[13];
    const float* b1  = (const float*)d_in[14];
    const float* W2  = (const float*)d_in[15];
    const float* b2  = (const float*)d_in[16];
    float* out = (float*)d_out;

    size_t kp_smem = (size_t)KP_SMEM_F2 * sizeof(float2);
    cudaFuncSetAttribute(k_kpipe, cudaFuncAttributeMaxDynamicSharedMemorySize, (int)kp_smem);

    k_ln<<<NROWS, 128>>>(x, nw, nb);
    k_kpipe<<<1, 1024, kp_smem>>>(lre, lim, pre, pim, bre, bim, ls, cre, cim);
    k_conv<<<576, 256>>>();
    k_gelu<<<2048, 256>>>(dd);
    k_gemm<<<dim3(32, 8), 256>>>(W1, W2, b1, b2, x, out);
}

// round 9
// speedup vs baseline: 1.4390x; 1.4390x over previous
#include <cuda_runtime.h>

#define H 512
#define LSEQ 1024
#define NROWS 4096
#define NST 64

typedef unsigned long long u64;

// ---- packed f32x2 (FFMA2) helpers ----
__device__ __forceinline__ u64 pack2(float x, float y) {
    u64 r; asm("mov.b64 %0,{%1,%2};" : "=l"(r) : "f"(x), "f"(y)); return r;
}
__device__ __forceinline__ u64 dup2(float x) { return pack2(x, x); }
__device__ __forceinline__ void unpack2(u64 v, float& x, float& y) {
    asm("mov.b64 {%0,%1},%2;" : "=f"(x), "=f"(y) : "l"(v));
}
__device__ __forceinline__ void fma2(u64& d, u64 a, u64 b) {
    asm("fma.rn.f32x2 %0,%1,%2,%0;" : "+l"(d) : "l"(a), "l"(b));
}

// ---- complex helpers ----
__device__ __forceinline__ float2 cmul(float2 a, float2 b) {
    return make_float2(a.x*b.x - a.y*b.y, a.x*b.y + a.y*b.x);
}
__device__ __forceinline__ float2 cadd(float2 a, float2 b) { return make_float2(a.x+b.x, a.y+b.y); }
__device__ __forceinline__ float2 csub(float2 a, float2 b) { return make_float2(a.x-b.x, a.y-b.y); }
__device__ __forceinline__ float2 cscale(float2 a, float s) { return make_float2(a.x*s, a.y*s); }
__device__ __forceinline__ float2 cinv(float2 d) {
    float inv = 1.f / (d.x*d.x + d.y*d.y);
    return make_float2(d.x*inv, -d.y*inv);
}

// ---- scratch: device globals ----
__device__ float  g_xn[NROWS * H];
__device__ float  g_yg[NROWS * H];
__device__ float  g_part[8][NROWS * H];
__device__ float2 g_M[2][NST * NST];    // dense Ab^(2^j), ping-pong
__device__ float2 g_MT[2][NST * NST];   // transposed copies
__device__ float2 g_S[NST * NST];       // S[k][n] = (Ab^k Bb)[n]
__device__ float  g_K[LSEQ];

// ================= LayerNorm =================
__global__ void k_ln(const float* __restrict__ x, const float* __restrict__ w,
                     const float* __restrict__ bi) {
    int row = blockIdx.x;
    int t = threadIdx.x;  // 128 threads, float4 each
    float4 v = ((const float4*)(x + (size_t)row * H))[t];
    float s  = v.x + v.y + v.z + v.w;
    float ss = v.x*v.x + v.y*v.y + v.z*v.z + v.w*v.w;
    __shared__ float rs[4], rss[4];
#pragma unroll
    for (int o = 16; o > 0; o >>= 1) {
        s  += __shfl_down_sync(0xffffffffu, s, o);
        ss += __shfl_down_sync(0xffffffffu, ss, o);
    }
    if ((t & 31) == 0) { rs[t >> 5] = s; rss[t >> 5] = ss; }
    __syncthreads();
    float sum = rs[0] + rs[1] + rs[2] + rs[3];
    float sq  = rss[0] + rss[1] + rss[2] + rss[3];
    float mu = sum * (1.f / H);
    float var = sq * (1.f / H) - mu * mu;
    float rstd = rsqrtf(var + 1e-5f);
    float4 wv = ((const float4*)w)[t];
    float4 bv = ((const float4*)bi)[t];
    float4 o;
    o.x = (v.x - mu) * rstd * wv.x + bv.x;
    o.y = (v.y - mu) * rstd * wv.y + bv.y;
    o.z = (v.z - mu) * rstd * wv.z + bv.z;
    o.w = (v.w - mu) * rstd * wv.w + bv.w;
    ((float4*)(g_xn + (size_t)row * H))[t] = o;
}

// ================= S4 setup (64 threads): Ab, Ab^T, s_0 =================
__device__ __forceinline__ float2 reduce64(float2 val, float2* red) {
    int i = threadIdx.x;
#pragma unroll
    for (int o = 16; o > 0; o >>= 1) {
        val.x += __shfl_down_sync(0xffffffffu, val.x, o);
        val.y += __shfl_down_sync(0xffffffffu, val.y, o);
    }
    if ((i & 31) == 0) red[i >> 5] = val;
    __syncthreads();
    float2 r = cadd(red[0], red[1]);
    __syncthreads();
    return r;
}

__global__ void k_setup(const float* lre, const float* lim, const float* pre, const float* pim,
                        const float* bre, const float* bim, const float* logstep) {
    int i = threadIdx.x;  // 64 threads
    __shared__ float2 sh_v[NST];
    __shared__ float2 red[2];
    float dt = expf(logstep[0]);
    float w0 = 2.f / dt;
    float2 lam = make_float2(lre[i], lim[i]);
    float2 p   = make_float2(pre[i], pim[i]);
    float2 bb  = make_float2(bre[i], bim[i]);
    float2 D  = cinv(make_float2(w0 - lam.x, -lam.y));
    float2 d0 = make_float2(w0 + lam.x, lam.y);
    float pn2 = p.x*p.x + p.y*p.y;
    float2 sig = reduce64(cscale(D, pn2), red);
    float2 alpha = cinv(make_float2(1.f + sig.x, sig.y));
    float2 u = cmul(D, p);
    float2 g = cmul(D, d0);
    float2 as = cmul(alpha, sig);
    float2 coef = csub(make_float2(as.x - 1.f, as.y), cmul(alpha, g));
    float2 v = cmul(make_float2(p.x, -p.y), coef);
    float2 Db = cmul(D, bb);
    float2 tau = reduce64(cmul(make_float2(p.x, -p.y), Db), red);
    float2 Bv = cscale(csub(Db, cmul(cmul(alpha, tau), u)), 2.f);
    sh_v[i] = v;
    __syncthreads();
    // Ab[i][j] = u_i * v_j + delta_ij * g_i ; also transposed copy
    for (int j = 0; j < NST; j++) {
        float2 e = cmul(u, sh_v[j]);
        if (j == i) e = cadd(e, g);
        g_M[0][i * NST + j] = e;
        g_MT[0][j * NST + i] = e;
    }
    g_S[0 * NST + i] = Bv;  // s_0 = Bb
}

// ================= squaring + S doubling in one launch =================
// blocks [0,64): Mout = Min*Min (row blk), also MoutT.
// blocks [64,64+r): s_{k+r} = Min * s_k  (Min = Ab^(2^j), r = 2^j)
__global__ void __launch_bounds__(256, 4) k_sq2(int srcsel, int r) {
    const float2* Min  = g_M[srcsel];
    const float2* MinT = g_MT[srcsel];
    float2* Mout  = g_M[srcsel ^ 1];
    float2* MoutT = g_MT[srcsel ^ 1];
    __shared__ float2 vec[NST];
    __shared__ float2 part[3][NST];
    int blk = blockIdx.x, tid = threadIdx.x;
    int j = tid & 63, q = tid >> 6;
    const float2 zero = make_float2(0.f, 0.f);
    if (blk < 64) {
        if (tid < NST) vec[tid] = Min[blk * NST + tid];
        __syncthreads();
        float2 acc = zero;
#pragma unroll
        for (int nn = 0; nn < 16; nn++) {
            int n = q * 16 + nn;
            acc = cadd(acc, cmul(vec[n], Min[n * NST + j]));
        }
        if (q) part[q - 1][j] = acc;
        __syncthreads();
        if (q == 0) {
            acc = cadd(acc, cadd(part[0][j], cadd(part[1][j], part[2][j])));
            Mout[blk * NST + j] = acc;
            MoutT[j * NST + blk] = acc;
        }
    } else {
        int k = blk - 64;  // k < r
        if (tid < NST) vec[tid] = g_S[k * NST + tid];
        __syncthreads();
        float2 acc = zero;
#pragma unroll
        for (int nn = 0; nn < 16; nn++) {
            int n = q * 16 + nn;
            // M[j][n] = MinT[n][j]  (coalesced across j)
            acc = cadd(acc, cmul(vec[n], MinT[n * NST + j]));
        }
        if (q) part[q - 1][j] = acc;
        __syncthreads();
        if (q == 0) {
            acc = cadd(acc, cadd(part[0][j], cadd(part[1][j], part[2][j])));
            g_S[(k + r) * NST + j] = acc;
        }
    }
}

// ================= K tail: r-chain + cross product (1 block, 1024 thr) =================
// smem: ST[n*65+k] (4160), Ms[n*65+i] (4160), Rm[m*64+n] (1024), Rc(64), Rn(64)
#define KT_SMEM_F2 (4160 + 4160 + 1024 + 64 + 64)
__global__ void __launch_bounds__(1024, 1) k_ktail(const float* cre, const float* cim) {
    extern __shared__ float2 sm[];
    float2* ST = sm;
    float2* Ms = ST + 4160;
    float2* Rm = Ms + 4160;
    float2* Rc = Rm + 1024;
    float2* Rn = Rc + 64;
    int tid = threadIdx.x;
    const float2 zero = make_float2(0.f, 0.f);
    // load S transposed + M (= Ab^64, buffer 0 after 6 squarings)
    for (int e = tid; e < NST * NST; e += 1024) {
        int k = e >> 6, n = e & 63;
        ST[n * 65 + k] = g_S[e];
        Ms[k * 65 + n] = g_M[0][e];  // Ms[a*65+b] = M[?]: e = k*64+n -> M[k][n] stored at [k][n]
    }
    if (tid < NST) Rc[tid] = make_float2(cre[tid], cim[tid]);
    __syncthreads();
    // r-chain: rn[i] = sum_n M[n][i] * r[n]  -> reads Ms[n*65+i]
    int i = tid >> 4, q = tid & 15;
    for (int m = 0; m < 16; m++) {
        if (tid < NST) Rm[m * NST + tid] = Rc[tid];
        float2 acc = zero;
#pragma unroll
        for (int nn = 0; nn < 4; nn++) {
            int n = q * 4 + nn;
            acc = cadd(acc, cmul(Rc[n], Ms[n * 65 + i]));
        }
#pragma unroll
        for (int o = 8; o > 0; o >>= 1) {
            acc.x += __shfl_down_sync(0xffffffffu, acc.x, o, 16);
            acc.y += __shfl_down_sync(0xffffffffu, acc.y, o, 16);
        }
        if (q == 0) Rn[i] = acc;
        __syncthreads();
        if (tid < NST) Rc[tid] = Rn[tid];
        __syncthreads();
    }
    // K[64m+k] = Re( sum_n Rm[m][n] * S[k][n] )
    int m = tid >> 6, k = tid & 63;
    float acc = 0.f;
#pragma unroll 8
    for (int n = 0; n < NST; n++) {
        float2 a = Rm[m * NST + n];   // broadcast within warp
        float2 s = ST[n * 65 + k];    // conflict-free
        acc += a.x * s.x - a.y * s.y;
    }
    g_K[m * NST + k] = acc;
}

// ================= causal Toeplitz conv, split-buffer partials =================
__global__ void __launch_bounds__(256, 2) k_conv() {
    int idx = blockIdx.x;
    int b = idx / 144;
    int rem = idx - b * 144;
    int hT = rem / 36;
    int pr = rem - hT * 36;
    int tT = 0;
    while ((tT + 1) * (tT + 2) / 2 <= pr) tT++;
    int sT = pr - tT * (tT + 1) / 2;
    int t0 = tT * 128, s0 = sT * 128, h0 = hT * 128;
    int D0 = t0 - s0;

    __shared__ float Ks[264];
    __shared__ float Xs[32][128];
    const float* X = g_xn + (size_t)(b * LSEQ) * H;
    int tid = threadIdx.x;
    for (int jj = tid; jj < 264; jj += 256) {
        int d = D0 + jj - 131;
        Ks[jj] = (d >= 0 && d < LSEQ) ? g_K[d] : 0.f;
    }
    int ty = tid >> 4, tx = tid & 15;
    u64 acc[8][4];
#pragma unroll
    for (int r = 0; r < 8; r++)
#pragma unroll
        for (int c = 0; c < 4; c++) acc[r][c] = 0ull;

    const float* KSp = Ks + 131 + ty * 8;

    for (int ch = 0; ch < 4; ch++) {
        __syncthreads();
        {
            int rr = tid >> 5;
            int cc = (tid & 31) * 4;
            const float* src = X + (size_t)(s0 + ch * 32 + rr) * H + h0 + cc;
#pragma unroll
            for (int k2 = 0; k2 < 4; k2++)
                *(float4*)&Xs[rr + k2 * 8][cc] = *(const float4*)(src + (size_t)(k2 * 8) * H);
        }
        __syncthreads();
        int base = -ch * 32;
        u64 a2[8];
#pragma unroll
        for (int r = 0; r < 8; r++) a2[r] = dup2(KSp[base + r]);
#pragma unroll
        for (int sl = 0; sl < 32; sl++) {
            u64 xv[4];
#pragma unroll
            for (int c = 0; c < 4; c++) xv[c] = *(const u64*)&Xs[sl][tx * 2 + c * 32];
#pragma unroll
            for (int r = 0; r < 8; r++)
#pragma unroll
                for (int c = 0; c < 4; c++) fma2(acc[r][c], a2[r], xv[c]);
#pragma unroll
            for (int r = 7; r > 0; r--) a2[r] = a2[r - 1];
            a2[0] = dup2(KSp[base - sl - 1]);
        }
    }
    float* P = g_part[sT] + ((size_t)(b * LSEQ) + t0) * H + h0;
#pragma unroll
    for (int r = 0; r < 8; r++) {
        float* Pr = P + (size_t)(ty * 8 + r) * H + tx * 2;
#pragma unroll
        for (int c = 0; c < 4; c++) {
            float va, vb; unpack2(acc[r][c], va, vb);
            *(float2*)(Pr + c * 32) = make_float2(va, vb);
        }
    }
}

// ================= split reduce + d*xn + GELU =================
__global__ void k_gelu(const float* __restrict__ dscale) {
    int idx = blockIdx.x * 256 + threadIdx.x;
    int row = idx >> 7, c4 = idx & 127;
    int t = row & (LSEQ - 1);
    int tT = t >> 7;
    size_t off = (size_t)row * H + c4 * 4;
    float4 s = make_float4(0.f, 0.f, 0.f, 0.f);
    for (int j = 0; j <= tT; j++) {
        float4 p = *(const float4*)(g_part[j] + off);
        s.x += p.x; s.y += p.y; s.z += p.z; s.w += p.w;
    }
    float dv = dscale[0];
    float4 xn = *(const float4*)(g_xn + off);
    float y0 = s.x + dv * xn.x, y1 = s.y + dv * xn.y;
    float y2 = s.z + dv * xn.z, y3 = s.w + dv * xn.w;
    float4 o;
    float z;
    z = 0.7978845608f * (y0 + 0.044715f * y0 * y0 * y0); o.x = y0 / (1.f + __expf(-2.f * z));
    z = 0.7978845608f * (y1 + 0.044715f * y1 * y1 * y1); o.y = y1 / (1.f + __expf(-2.f * z));
    z = 0.7978845608f * (y2 + 0.044715f * y2 * y2 * y2); o.z = y2 / (1.f + __expf(-2.f * z));
    z = 0.7978845608f * (y3 + 0.044715f * y3 * y3 * y3); o.w = y3 / (1.f + __expf(-2.f * z));
    *(float4*)(g_yg + off) = o;
}

// ================= fused dual GEMM + sigmoid gate + residual =================
__global__ void __launch_bounds__(256, 2) k_gemm(
    const float* __restrict__ W1, const float* __restrict__ W2,
    const float* __restrict__ b1, const float* __restrict__ b2,
    const float* __restrict__ skip, float* __restrict__ out) {
    __shared__ float As[32][132];
    __shared__ float Bs[32][132];
    int r0 = blockIdx.x * 128, o0 = blockIdx.y * 64;
    int tid = threadIdx.x, ty = tid >> 4, tx = tid & 15;
    int rr = tid & 127, half = tid >> 7;
    u64 acc[8][4];
#pragma unroll
    for (int r = 0; r < 8; r++)
#pragma unroll
        for (int j = 0; j < 4; j++) acc[r][j] = 0ull;
    const float* Bsrc = (rr < 64) ? (W1 + (size_t)(o0 + rr) * H)
                                  : (W2 + (size_t)(o0 + rr - 64) * H);
    const float* Asrc = g_yg + (size_t)(r0 + rr) * H;

    for (int kc = 0; kc < 16; kc++) {
        __syncthreads();
        int kb = kc * 32 + half * 16;
#pragma unroll
        for (int q = 0; q < 4; q++) {
            float4 av = *(const float4*)(Asrc + kb + q * 4);
            int kk = half * 16 + q * 4;
            As[kk + 0][rr] = av.x; As[kk + 1][rr] = av.y;
            As[kk + 2][rr] = av.z; As[kk + 3][rr] = av.w;
            float4 bv = *(const float4*)(Bsrc + kb + q * 4);
            Bs[kk + 0][rr] = bv.x; Bs[kk + 1][rr] = bv.y;
            Bs[kk + 2][rr] = bv.z; Bs[kk + 3][rr] = bv.w;
        }
        __syncthreads();
#pragma unroll
        for (int kk = 0; kk < 32; kk++) {
            float4 a0 = *(const float4*)&As[kk][ty * 8];
            float4 a1 = *(const float4*)&As[kk][ty * 8 + 4];
            u64 bb[4];
#pragma unroll
            for (int j = 0; j < 4; j++) bb[j] = *(const u64*)&Bs[kk][tx * 2 + j * 32];
            u64 ad[8] = { dup2(a0.x), dup2(a0.y), dup2(a0.z), dup2(a0.w),
                          dup2(a1.x), dup2(a1.y), dup2(a1.z), dup2(a1.w) };
#pragma unroll
            for (int r = 0; r < 8; r++)
#pragma unroll
                for (int j = 0; j < 4; j++) fma2(acc[r][j], ad[r], bb[j]);
        }
    }
#pragma unroll
    for (int r = 0; r < 8; r++) {
        int row = r0 + ty * 8 + r;
        const float* sk = skip + (size_t)row * H;
        float* op = out + (size_t)row * H;
#pragma unroll
        for (int j = 0; j < 2; j++) {
            int o = o0 + tx * 2 + j * 32;
            float p1a, p1b, p2a, p2b;
            unpack2(acc[r][j], p1a, p1b);
            unpack2(acc[r][j + 2], p2a, p2b);
            float v1 = p1a + b1[o], v2 = p1b + b1[o + 1];
            float g1 = p2a + b2[o], g2 = p2b + b2[o + 1];
            float o1 = sk[o]     + v1 / (1.f + __expf(-g1));
            float o2 = sk[o + 1] + v2 / (1.f + __expf(-g2));
            *(float2*)(op + o) = make_float2(o1, o2);
        }
    }
}

extern "C" void kernel_launch(void* const* d_in, const int* in_sizes, int n_in,
                              void* d_out, int out_size) {
    const float* x   = (const float*)d_in[0];
    const float* nw  = (const float*)d_in[1];
    const float* nb  = (const float*)d_in[2];
    const float* lre = (const float*)d_in[3];
    const float* lim = (const float*)d_in[4];
    const float* pre = (const float*)d_in[5];
    const float* pim = (const float*)d_in[6];
    const float* bre = (const float*)d_in[7];
    const float* bim = (const float*)d_in[8];
    const float* cre = (const float*)d_in[9];
    const float* cim = (const float*)d_in[10];
    const float* dd  = (const float*)d_in[11];
    const float* ls  = (const float*)d_in[12];
    const float* W1  = (const float*)d_in[13];
    const float* b1  = (const float*)d_in[14];
    const float* W2  = (const float*)d_in[15];
    const float* b2  = (const float*)d_in[16];
    float* out = (float*)d_out;

    size_t kt_smem = (size_t)KT_SMEM_F2 * sizeof(float2);
    cudaFuncSetAttribute(k_ktail, cudaFuncAttributeMaxDynamicSharedMemorySize, (int)kt_smem);

    k_ln<<<NROWS, 128>>>(x, nw, nb);
    k_setup<<<1, 64>>>(lre, lim, pre, pim, bre, bim, ls);
    for (int j = 0; j < 6; j++)
        k_sq2<<<64 + (1 << j), 256>>>(j & 1, 1 << j);
    k_ktail<<<1, 1024, kt_smem>>>(cre, cim);
    k_conv<<<576, 256>>>();
    k_gelu<<<2048, 256>>>(dd);
    k_gemm<<<dim3(32, 8), 256>>>(W1, W2, b1, b2, x, out);
}

// round 10
// speedup vs baseline: 2.1035x; 1.4618x over previous
#include <cuda_runtime.h>

#define H 512
#define LSEQ 1024
#define NROWS 4096
#define NST 64

typedef unsigned long long u64;

// ---- packed f32x2 (FFMA2) helpers ----
__device__ __forceinline__ u64 pack2(float x, float y) {
    u64 r; asm("mov.b64 %0,{%1,%2};" : "=l"(r) : "f"(x), "f"(y)); return r;
}
__device__ __forceinline__ u64 dup2(float x) { return pack2(x, x); }
__device__ __forceinline__ void unpack2(u64 v, float& x, float& y) {
    asm("mov.b64 {%0,%1},%2;" : "=f"(x), "=f"(y) : "l"(v));
}
__device__ __forceinline__ void fma2(u64& d, u64 a, u64 b) {
    asm("fma.rn.f32x2 %0,%1,%2,%0;" : "+l"(d) : "l"(a), "l"(b));
}

// ---- complex helpers ----
__device__ __forceinline__ float2 cmul(float2 a, float2 b) {
    return make_float2(a.x*b.x - a.y*b.y, a.x*b.y + a.y*b.x);
}
__device__ __forceinline__ float2 cadd(float2 a, float2 b) { return make_float2(a.x+b.x, a.y+b.y); }
__device__ __forceinline__ float2 csub(float2 a, float2 b) { return make_float2(a.x-b.x, a.y-b.y); }
__device__ __forceinline__ float2 cscale(float2 a, float s) { return make_float2(a.x*s, a.y*s); }
__device__ __forceinline__ float2 cinv(float2 d) {
    float inv = 1.f / (d.x*d.x + d.y*d.y);
    return make_float2(d.x*inv, -d.y*inv);
}

// ---- tf32 convert ----
__device__ __forceinline__ unsigned f2tf(float x) {
    unsigned u; asm("cvt.rna.tf32.f32 %0,%1;" : "=r"(u) : "f"(x)); return u;
}

// ---- scratch: device globals ----
__device__ float  g_xn[NROWS * H];
__device__ float  g_yg[NROWS * H];
__device__ float  g_part[8][NROWS * H];
__device__ float2 g_M[2][NST * NST];    // dense Ab^(2^j), ping-pong
__device__ float2 g_MT[2][NST * NST];   // transposed copies
__device__ float2 g_S[NST * NST];       // S[k][n] = (Ab^k Bb)[n]
__device__ float  g_K[LSEQ];

// ================= LayerNorm =================
__global__ void k_ln(const float* __restrict__ x, const float* __restrict__ w,
                     const float* __restrict__ bi) {
    int row = blockIdx.x;
    int t = threadIdx.x;  // 128 threads, float4 each
    float4 v = ((const float4*)(x + (size_t)row * H))[t];
    float s  = v.x + v.y + v.z + v.w;
    float ss = v.x*v.x + v.y*v.y + v.z*v.z + v.w*v.w;
    __shared__ float rs[4], rss[4];
#pragma unroll
    for (int o = 16; o > 0; o >>= 1) {
        s  += __shfl_down_sync(0xffffffffu, s, o);
        ss += __shfl_down_sync(0xffffffffu, ss, o);
    }
    if ((t & 31) == 0) { rs[t >> 5] = s; rss[t >> 5] = ss; }
    __syncthreads();
    float sum = rs[0] + rs[1] + rs[2] + rs[3];
    float sq  = rss[0] + rss[1] + rss[2] + rss[3];
    float mu = sum * (1.f / H);
    float var = sq * (1.f / H) - mu * mu;
    float rstd = rsqrtf(var + 1e-5f);
    float4 wv = ((const float4*)w)[t];
    float4 bv = ((const float4*)bi)[t];
    float4 o;
    o.x = (v.x - mu) * rstd * wv.x + bv.x;
    o.y = (v.y - mu) * rstd * wv.y + bv.y;
    o.z = (v.z - mu) * rstd * wv.z + bv.z;
    o.w = (v.w - mu) * rstd * wv.w + bv.w;
    ((float4*)(g_xn + (size_t)row * H))[t] = o;
}

// ================= S4 setup (64 threads): Ab, Ab^T, s_0 =================
__device__ __forceinline__ float2 reduce64(float2 val, float2* red) {
    int i = threadIdx.x;
#pragma unroll
    for (int o = 16; o > 0; o >>= 1) {
        val.x += __shfl_down_sync(0xffffffffu, val.x, o);
        val.y += __shfl_down_sync(0xffffffffu, val.y, o);
    }
    if ((i & 31) == 0) red[i >> 5] = val;
    __syncthreads();
    float2 r = cadd(red[0], red[1]);
    __syncthreads();
    return r;
}

__global__ void k_setup(const float* lre, const float* lim, const float* pre, const float* pim,
                        const float* bre, const float* bim, const float* logstep) {
    int i = threadIdx.x;  // 64 threads
    __shared__ float2 sh_v[NST];
    __shared__ float2 red[2];
    float dt = expf(logstep[0]);
    float w0 = 2.f / dt;
    float2 lam = make_float2(lre[i], lim[i]);
    float2 p   = make_float2(pre[i], pim[i]);
    float2 bb  = make_float2(bre[i], bim[i]);
    float2 D  = cinv(make_float2(w0 - lam.x, -lam.y));
    float2 d0 = make_float2(w0 + lam.x, lam.y);
    float pn2 = p.x*p.x + p.y*p.y;
    float2 sig = reduce64(cscale(D, pn2), red);
    float2 alpha = cinv(make_float2(1.f + sig.x, sig.y));
    float2 u = cmul(D, p);
    float2 g = cmul(D, d0);
    float2 as = cmul(alpha, sig);
    float2 coef = csub(make_float2(as.x - 1.f, as.y), cmul(alpha, g));
    float2 v = cmul(make_float2(p.x, -p.y), coef);
    float2 Db = cmul(D, bb);
    float2 tau = reduce64(cmul(make_float2(p.x, -p.y), Db), red);
    float2 Bv = cscale(csub(Db, cmul(cmul(alpha, tau), u)), 2.f);
    sh_v[i] = v;
    __syncthreads();
    // Ab[i][j] = u_i * v_j + delta_ij * g_i ; also transposed copy
    for (int j = 0; j < NST; j++) {
        float2 e = cmul(u, sh_v[j]);
        if (j == i) e = cadd(e, g);
        g_M[0][i * NST + j] = e;
        g_MT[0][j * NST + i] = e;
    }
    g_S[0 * NST + i] = Bv;  // s_0 = Bb
}

// ================= squaring + S doubling in one launch =================
__global__ void __launch_bounds__(256, 4) k_sq2(int srcsel, int r) {
    const float2* Min  = g_M[srcsel];
    const float2* MinT = g_MT[srcsel];
    float2* Mout  = g_M[srcsel ^ 1];
    float2* MoutT = g_MT[srcsel ^ 1];
    __shared__ float2 vec[NST];
    __shared__ float2 part[3][NST];
    int blk = blockIdx.x, tid = threadIdx.x;
    int j = tid & 63, q = tid >> 6;
    const float2 zero = make_float2(0.f, 0.f);
    if (blk < 64) {
        if (tid < NST) vec[tid] = Min[blk * NST + tid];
        __syncthreads();
        float2 acc = zero;
#pragma unroll
        for (int nn = 0; nn < 16; nn++) {
            int n = q * 16 + nn;
            acc = cadd(acc, cmul(vec[n], Min[n * NST + j]));
        }
        if (q) part[q - 1][j] = acc;
        __syncthreads();
        if (q == 0) {
            acc = cadd(acc, cadd(part[0][j], cadd(part[1][j], part[2][j])));
            Mout[blk * NST + j] = acc;
            MoutT[j * NST + blk] = acc;
        }
    } else {
        int k = blk - 64;  // k < r
        if (tid < NST) vec[tid] = g_S[k * NST + tid];
        __syncthreads();
        float2 acc = zero;
#pragma unroll
        for (int nn = 0; nn < 16; nn++) {
            int n = q * 16 + nn;
            acc = cadd(acc, cmul(vec[n], MinT[n * NST + j]));
        }
        if (q) part[q - 1][j] = acc;
        __syncthreads();
        if (q == 0) {
            acc = cadd(acc, cadd(part[0][j], cadd(part[1][j], part[2][j])));
            g_S[(k + r) * NST + j] = acc;
        }
    }
}

// ================= K tail: r-chain + cross product (1 block, 1024 thr) =================
#define KT_SMEM_F2 (4160 + 4160 + 1024 + 64 + 64)
__global__ void __launch_bounds__(1024, 1) k_ktail(const float* cre, const float* cim) {
    extern __shared__ float2 sm[];
    float2* ST = sm;
    float2* Ms = ST + 4160;
    float2* Rm = Ms + 4160;
    float2* Rc = Rm + 1024;
    float2* Rn = Rc + 64;
    int tid = threadIdx.x;
    const float2 zero = make_float2(0.f, 0.f);
    for (int e = tid; e < NST * NST; e += 1024) {
        int k = e >> 6, n = e & 63;
        ST[n * 65 + k] = g_S[e];
        Ms[k * 65 + n] = g_M[0][e];
    }
    if (tid < NST) Rc[tid] = make_float2(cre[tid], cim[tid]);
    __syncthreads();
    int i = tid >> 4, q = tid & 15;
    for (int m = 0; m < 16; m++) {
        if (tid < NST) Rm[m * NST + tid] = Rc[tid];
        float2 acc = zero;
#pragma unroll
        for (int nn = 0; nn < 4; nn++) {
            int n = q * 4 + nn;
            acc = cadd(acc, cmul(Rc[n], Ms[n * 65 + i]));
        }
#pragma unroll
        for (int o = 8; o > 0; o >>= 1) {
            acc.x += __shfl_down_sync(0xffffffffu, acc.x, o, 16);
            acc.y += __shfl_down_sync(0xffffffffu, acc.y, o, 16);
        }
        if (q == 0) Rn[i] = acc;
        __syncthreads();
        if (tid < NST) Rc[tid] = Rn[tid];
        __syncthreads();
    }
    int m = tid >> 6, k = tid & 63;
    float acc = 0.f;
#pragma unroll 8
    for (int n = 0; n < NST; n++) {
        float2 a = Rm[m * NST + n];
        float2 s = ST[n * 65 + k];
        acc += a.x * s.x - a.y * s.y;
    }
    g_K[m * NST + k] = acc;
}

// ================= causal Toeplitz conv, split-buffer partials =================
__global__ void __launch_bounds__(256, 2) k_conv() {
    int idx = blockIdx.x;
    int b = idx / 144;
    int rem = idx - b * 144;
    int hT = rem / 36;
    int pr = rem - hT * 36;
    int tT = 0;
    while ((tT + 1) * (tT + 2) / 2 <= pr) tT++;
    int sT = pr - tT * (tT + 1) / 2;
    int t0 = tT * 128, s0 = sT * 128, h0 = hT * 128;
    int D0 = t0 - s0;

    __shared__ float Ks[264];
    __shared__ float Xs[32][128];
    const float* X = g_xn + (size_t)(b * LSEQ) * H;
    int tid = threadIdx.x;
    for (int jj = tid; jj < 264; jj += 256) {
        int d = D0 + jj - 131;
        Ks[jj] = (d >= 0 && d < LSEQ) ? g_K[d] : 0.f;
    }
    int ty = tid >> 4, tx = tid & 15;
    u64 acc[8][4];
#pragma unroll
    for (int r = 0; r < 8; r++)
#pragma unroll
        for (int c = 0; c < 4; c++) acc[r][c] = 0ull;

    const float* KSp = Ks + 131 + ty * 8;

    for (int ch = 0; ch < 4; ch++) {
        __syncthreads();
        {
            int rr = tid >> 5;
            int cc = (tid & 31) * 4;
            const float* src = X + (size_t)(s0 + ch * 32 + rr) * H + h0 + cc;
#pragma unroll
            for (int k2 = 0; k2 < 4; k2++)
                *(float4*)&Xs[rr + k2 * 8][cc] = *(const float4*)(src + (size_t)(k2 * 8) * H);
        }
        __syncthreads();
        int base = -ch * 32;
        u64 a2[8];
#pragma unroll
        for (int r = 0; r < 8; r++) a2[r] = dup2(KSp[base + r]);
#pragma unroll
        for (int sl = 0; sl < 32; sl++) {
            u64 xv[4];
#pragma unroll
            for (int c = 0; c < 4; c++) xv[c] = *(const u64*)&Xs[sl][tx * 2 + c * 32];
#pragma unroll
            for (int r = 0; r < 8; r++)
#pragma unroll
                for (int c = 0; c < 4; c++) fma2(acc[r][c], a2[r], xv[c]);
#pragma unroll
            for (int r = 7; r > 0; r--) a2[r] = a2[r - 1];
            a2[0] = dup2(KSp[base - sl - 1]);
        }
    }
    float* P = g_part[sT] + ((size_t)(b * LSEQ) + t0) * H + h0;
#pragma unroll
    for (int r = 0; r < 8; r++) {
        float* Pr = P + (size_t)(ty * 8 + r) * H + tx * 2;
#pragma unroll
        for (int c = 0; c < 4; c++) {
            float va, vb; unpack2(acc[r][c], va, vb);
            *(float2*)(Pr + c * 32) = make_float2(va, vb);
        }
    }
}

// ================= split reduce + d*xn + GELU =================
__global__ void k_gelu(const float* __restrict__ dscale) {
    int idx = blockIdx.x * 256 + threadIdx.x;
    int row = idx >> 7, c4 = idx & 127;
    int t = row & (LSEQ - 1);
    int tT = t >> 7;
    size_t off = (size_t)row * H + c4 * 4;
    float4 s = make_float4(0.f, 0.f, 0.f, 0.f);
    for (int j = 0; j <= tT; j++) {
        float4 p = *(const float4*)(g_part[j] + off);
        s.x += p.x; s.y += p.y; s.z += p.z; s.w += p.w;
    }
    float dv = dscale[0];
    float4 xn = *(const float4*)(g_xn + off);
    float y0 = s.x + dv * xn.x, y1 = s.y + dv * xn.y;
    float y2 = s.z + dv * xn.z, y3 = s.w + dv * xn.w;
    float4 o;
    float z;
    z = 0.7978845608f * (y0 + 0.044715f * y0 * y0 * y0); o.x = y0 / (1.f + __expf(-2.f * z));
    z = 0.7978845608f * (y1 + 0.044715f * y1 * y1 * y1); o.y = y1 / (1.f + __expf(-2.f * z));
    z = 0.7978845608f * (y2 + 0.044715f * y2 * y2 * y2); o.z = y2 / (1.f + __expf(-2.f * z));
    z = 0.7978845608f * (y3 + 0.044715f * y3 * y3 * y3); o.w = y3 / (1.f + __expf(-2.f * z));
    *(float4*)(g_yg + off) = o;
}

// ================= dual GEMM on tensor cores (tf32 mma.sync) =================
// Block: 128 rows x 64 out-cols, computing BOTH proj and gate (N_comb=128).
// Combined-n mapping: n_comb -> sub=n_comb&15: sub<8 => W1, else W2;
//                     outcol = o0 + (n_comb>>4)*8 + (sub&7)
// So each warp's ntile pairs (0,1) and (2,3) hold proj/gate of the SAME cols.
// Smem pitch 36 floats => fragment LDS (g*36+t) hits all 32 banks once.
#define GM_SMEM_BYTES (2 * 2 * 4608 * 4)  // 2 bufs x (A 4608 + B 4608) uints

__device__ __forceinline__ void mma_tf32(float* c, const unsigned* a, const unsigned* b) {
    asm("mma.sync.aligned.m16n8k8.row.col.f32.tf32.tf32.f32 "
        "{%0,%1,%2,%3}, {%4,%5,%6,%7}, {%8,%9}, {%0,%1,%2,%3};"
        : "+f"(c[0]), "+f"(c[1]), "+f"(c[2]), "+f"(c[3])
        : "r"(a[0]), "r"(a[1]), "r"(a[2]), "r"(a[3]), "r"(b[0]), "r"(b[1]));
}

__global__ void __launch_bounds__(256) k_gemm(
    const float* __restrict__ W1, const float* __restrict__ W2,
    const float* __restrict__ b1, const float* __restrict__ b2,
    const float* __restrict__ skip, float* __restrict__ out) {
    extern __shared__ unsigned sh[];
    int r0 = blockIdx.x * 128, o0 = blockIdx.y * 64;
    int tid = threadIdx.x;
    int lane = tid & 31, warp = tid >> 5;
    int g = lane >> 2, t = lane & 3;
    int wm = warp & 1, wn = warp >> 1;

    // loader mapping: thread -> (row 0..127, seg 0..1), 16 floats per seg
    int lrow = tid >> 1, lseg = tid & 1;
    const float* Asrc = g_yg + (size_t)(r0 + lrow) * H + lseg * 16;
    int sub = lrow & 15;
    int outn = o0 + (lrow >> 4) * 8 + (sub & 7);
    const float* Bsrc = ((sub < 8) ? W1 : W2) + (size_t)outn * H + lseg * 16;
    unsigned woff = lrow * 36 + lseg * 16;

    float C[4][4][4];
#pragma unroll
    for (int a = 0; a < 4; a++)
#pragma unroll
        for (int b = 0; b < 4; b++)
#pragma unroll
            for (int c = 0; c < 4; c++) C[a][b][c] = 0.f;

    // prologue: chunk 0 -> buf 0
#pragma unroll
    for (int q = 0; q < 4; q++) {
        float4 va = *(const float4*)(Asrc + q * 4);
        uint4 ua = make_uint4(f2tf(va.x), f2tf(va.y), f2tf(va.z), f2tf(va.w));
        *(uint4*)&sh[woff + q * 4] = ua;
        float4 vb = *(const float4*)(Bsrc + q * 4);
        uint4 ub = make_uint4(f2tf(vb.x), f2tf(vb.y), f2tf(vb.z), f2tf(vb.w));
        *(uint4*)&sh[4608 + woff + q * 4] = ub;
    }
    __syncthreads();

    for (int ch = 0; ch < 16; ch++) {
        float4 stA[4], stB[4];
        if (ch < 15) {
            const float* pa = Asrc + (ch + 1) * 32;
            const float* pb = Bsrc + (ch + 1) * 32;
#pragma unroll
            for (int q = 0; q < 4; q++) { stA[q] = *(const float4*)(pa + q * 4);
                                          stB[q] = *(const float4*)(pb + q * 4); }
        }
        const unsigned* A = sh + (ch & 1) * 9216;
        const unsigned* B = A + 4608;
#pragma unroll
        for (int ks = 0; ks < 4; ks++) {
            int kk = ks * 8 + t;
            unsigned af[4][4], bf[4][2];
#pragma unroll
            for (int mt = 0; mt < 4; mt++) {
                const unsigned* p = A + (wm * 64 + mt * 16 + g) * 36 + kk;
                af[mt][0] = p[0]; af[mt][1] = p[8 * 36];
                af[mt][2] = p[4]; af[mt][3] = p[8 * 36 + 4];
            }
#pragma unroll
            for (int nt = 0; nt < 4; nt++) {
                const unsigned* p = B + (wn * 32 + nt * 8 + g) * 36 + kk;
                bf[nt][0] = p[0]; bf[nt][1] = p[4];
            }
#pragma unroll
            for (int mt = 0; mt < 4; mt++)
#pragma unroll
                for (int nt = 0; nt < 4; nt++)
                    mma_tf32(C[mt][nt], af[mt], bf[nt]);
        }
        if (ch < 15) {
            unsigned* dA = sh + ((ch + 1) & 1) * 9216 + woff;
            unsigned* dB = dA + 4608;
#pragma unroll
            for (int q = 0; q < 4; q++) {
                *(uint4*)(dA + q * 4) = make_uint4(f2tf(stA[q].x), f2tf(stA[q].y),
                                                   f2tf(stA[q].z), f2tf(stA[q].w));
                *(uint4*)(dB + q * 4) = make_uint4(f2tf(stB[q].x), f2tf(stB[q].y),
                                                   f2tf(stB[q].z), f2tf(stB[q].w));
            }
        }
        __syncthreads();
    }

    // epilogue: bias + sigmoid gate + residual
    float b1v[2][2], b2v[2][2];
#pragma unroll
    for (int p = 0; p < 2; p++) {
        int col = o0 + wn * 16 + p * 8 + t * 2;
        b1v[p][0] = b1[col]; b1v[p][1] = b1[col + 1];
        b2v[p][0] = b2[col]; b2v[p][1] = b2[col + 1];
    }
#pragma unroll
    for (int mt = 0; mt < 4; mt++) {
        int row = r0 + wm * 64 + mt * 16 + g;
#pragma unroll
        for (int p = 0; p < 2; p++) {
            int col = o0 + wn * 16 + p * 8 + t * 2;
            const float* pr = C[mt][2 * p];
            const float* ga = C[mt][2 * p + 1];
            // rows g and g+8
#pragma unroll
            for (int h = 0; h < 2; h++) {
                int rw = row + h * 8;
                float v0 = pr[h * 2 + 0] + b1v[p][0];
                float v1 = pr[h * 2 + 1] + b1v[p][1];
                float g0 = ga[h * 2 + 0] + b2v[p][0];
                float g1 = ga[h * 2 + 1] + b2v[p][1];
                float o0v = skip[(size_t)rw * H + col]     + v0 / (1.f + __expf(-g0));
                float o1v = skip[(size_t)rw * H + col + 1] + v1 / (1.f + __expf(-g1));
                *(float2*)(out + (size_t)rw * H + col) = make_float2(o0v, o1v);
            }
        }
    }
}

extern "C" void kernel_launch(void* const* d_in, const int* in_sizes, int n_in,
                              void* d_out, int out_size) {
    const float* x   = (const float*)d_in[0];
    const float* nw  = (const float*)d_in[1];
    const float* nb  = (const float*)d_in[2];
    const float* lre = (const float*)d_in[3];
    const float* lim = (const float*)d_in[4];
    const float* pre = (const float*)d_in[5];
    const float* pim = (const float*)d_in[6];
    const float* bre = (const float*)d_in[7];
    const float* bim = (const float*)d_in[8];
    const float* cre = (const float*)d_in[9];
    const float* cim = (const float*)d_in[10];
    const float* dd  = (const float*)d_in[11];
    const float* ls  = (const float*)d_in[12];
    const float* W1  = (const float*)d_in[13];
    const float* b1  = (const float*)d_in[14];
    const float* W2  = (const float*)d_in[15];
    const float* b2  = (const float*)d_in[16];
    float* out = (float*)d_out;

    size_t kt_smem = (size_t)KT_SMEM_F2 * sizeof(float2);
    cudaFuncSetAttribute(k_ktail, cudaFuncAttributeMaxDynamicSharedMemorySize, (int)kt_smem);
    cudaFuncSetAttribute(k_gemm, cudaFuncAttributeMaxDynamicSharedMemorySize, GM_SMEM_BYTES);

    k_ln<<<NROWS, 128>>>(x, nw, nb);
    k_setup<<<1, 64>>>(lre, lim, pre, pim, bre, bim, ls);
    for (int j = 0; j < 6; j++)
        k_sq2<<<64 + (1 << j), 256>>>(j & 1, 1 << j);
    k_ktail<<<1, 1024, kt_smem>>>(cre, cim);
    k_conv<<<576, 256>>>();
    k_gelu<<<2048, 256>>>(dd);
    k_gemm<<<dim3(32, 8), 256, GM_SMEM_BYTES>>>(W1, W2, b1, b2, x, out);
}

// round 11
// speedup vs baseline: 2.4397x; 1.1598x over previous
#include <cuda_runtime.h>

#define H 512
#define LSEQ 1024
#define NROWS 4096
#define NST 64

typedef unsigned long long u64;

// ---- packed f32x2 (FFMA2) helpers ----
__device__ __forceinline__ u64 pack2(float x, float y) {
    u64 r; asm("mov.b64 %0,{%1,%2};" : "=l"(r) : "f"(x), "f"(y)); return r;
}
__device__ __forceinline__ u64 dup2(float x) { return pack2(x, x); }
__device__ __forceinline__ void unpack2(u64 v, float& x, float& y) {
    asm("mov.b64 {%0,%1},%2;" : "=f"(x), "=f"(y) : "l"(v));
}
__device__ __forceinline__ void fma2(u64& d, u64 a, u64 b) {
    asm("fma.rn.f32x2 %0,%1,%2,%0;" : "+l"(d) : "l"(a), "l"(b));
}

// ---- complex helpers ----
__device__ __forceinline__ float2 cmul(float2 a, float2 b) {
    return make_float2(a.x*b.x - a.y*b.y, a.x*b.y + a.y*b.x);
}
__device__ __forceinline__ float2 cadd(float2 a, float2 b) { return make_float2(a.x+b.x, a.y+b.y); }
__device__ __forceinline__ float2 csub(float2 a, float2 b) { return make_float2(a.x-b.x, a.y-b.y); }
__device__ __forceinline__ float2 cscale(float2 a, float s) { return make_float2(a.x*s, a.y*s); }
__device__ __forceinline__ float2 cinv(float2 d) {
    float inv = 1.f / (d.x*d.x + d.y*d.y);
    return make_float2(d.x*inv, -d.y*inv);
}

// ---- tf32 convert ----
__device__ __forceinline__ unsigned f2tf(float x) {
    unsigned u; asm("cvt.rna.tf32.f32 %0,%1;" : "=r"(u) : "f"(x)); return u;
}

__device__ __forceinline__ void mma_tf32(float* c, const unsigned* a, const unsigned* b) {
    asm("mma.sync.aligned.m16n8k8.row.col.f32.tf32.tf32.f32 "
        "{%0,%1,%2,%3}, {%4,%5,%6,%7}, {%8,%9}, {%0,%1,%2,%3};"
        : "+f"(c[0]), "+f"(c[1]), "+f"(c[2]), "+f"(c[3])
        : "r"(a[0]), "r"(a[1]), "r"(a[2]), "r"(a[3]), "r"(b[0]), "r"(b[1]));
}

// ---- scratch: device globals ----
__device__ float  g_xn[NROWS * H];
__device__ float  g_yg[NROWS * H];
__device__ float  g_part[8][NROWS * H];
__device__ float2 g_M[2][NST * NST];    // dense Ab^(2^j), ping-pong
__device__ float2 g_MT[2][NST * NST];   // transposed copies
__device__ float2 g_S[NST * NST];       // S[k][n] = (Ab^k Bb)[n]
__device__ float  g_K[LSEQ];

// ================= LayerNorm =================
__global__ void k_ln(const float* __restrict__ x, const float* __restrict__ w,
                     const float* __restrict__ bi) {
    int row = blockIdx.x;
    int t = threadIdx.x;  // 128 threads, float4 each
    float4 v = ((const float4*)(x + (size_t)row * H))[t];
    float s  = v.x + v.y + v.z + v.w;
    float ss = v.x*v.x + v.y*v.y + v.z*v.z + v.w*v.w;
    __shared__ float rs[4], rss[4];
#pragma unroll
    for (int o = 16; o > 0; o >>= 1) {
        s  += __shfl_down_sync(0xffffffffu, s, o);
        ss += __shfl_down_sync(0xffffffffu, ss, o);
    }
    if ((t & 31) == 0) { rs[t >> 5] = s; rss[t >> 5] = ss; }
    __syncthreads();
    float sum = rs[0] + rs[1] + rs[2] + rs[3];
    float sq  = rss[0] + rss[1] + rss[2] + rss[3];
    float mu = sum * (1.f / H);
    float var = sq * (1.f / H) - mu * mu;
    float rstd = rsqrtf(var + 1e-5f);
    float4 wv = ((const float4*)w)[t];
    float4 bv = ((const float4*)bi)[t];
    float4 o;
    o.x = (v.x - mu) * rstd * wv.x + bv.x;
    o.y = (v.y - mu) * rstd * wv.y + bv.y;
    o.z = (v.z - mu) * rstd * wv.z + bv.z;
    o.w = (v.w - mu) * rstd * wv.w + bv.w;
    ((float4*)(g_xn + (size_t)row * H))[t] = o;
}

// ================= S4 setup (64 threads): Ab, Ab^T, s_0 =================
__device__ __forceinline__ float2 reduce64(float2 val, float2* red) {
    int i = threadIdx.x;
#pragma unroll
    for (int o = 16; o > 0; o >>= 1) {
        val.x += __shfl_down_sync(0xffffffffu, val.x, o);
        val.y += __shfl_down_sync(0xffffffffu, val.y, o);
    }
    if ((i & 31) == 0) red[i >> 5] = val;
    __syncthreads();
    float2 r = cadd(red[0], red[1]);
    __syncthreads();
    return r;
}

__global__ void k_setup(const float* lre, const float* lim, const float* pre, const float* pim,
                        const float* bre, const float* bim, const float* logstep) {
    int i = threadIdx.x;  // 64 threads
    __shared__ float2 sh_v[NST];
    __shared__ float2 red[2];
    float dt = expf(logstep[0]);
    float w0 = 2.f / dt;
    float2 lam = make_float2(lre[i], lim[i]);
    float2 p   = make_float2(pre[i], pim[i]);
    float2 bb  = make_float2(bre[i], bim[i]);
    float2 D  = cinv(make_float2(w0 - lam.x, -lam.y));
    float2 d0 = make_float2(w0 + lam.x, lam.y);
    float pn2 = p.x*p.x + p.y*p.y;
    float2 sig = reduce64(cscale(D, pn2), red);
    float2 alpha = cinv(make_float2(1.f + sig.x, sig.y));
    float2 u = cmul(D, p);
    float2 g = cmul(D, d0);
    float2 as = cmul(alpha, sig);
    float2 coef = csub(make_float2(as.x - 1.f, as.y), cmul(alpha, g));
    float2 v = cmul(make_float2(p.x, -p.y), coef);
    float2 Db = cmul(D, bb);
    float2 tau = reduce64(cmul(make_float2(p.x, -p.y), Db), red);
    float2 Bv = cscale(csub(Db, cmul(cmul(alpha, tau), u)), 2.f);
    sh_v[i] = v;
    __syncthreads();
    // Ab[i][j] = u_i * v_j + delta_ij * g_i ; also transposed copy
    for (int j = 0; j < NST; j++) {
        float2 e = cmul(u, sh_v[j]);
        if (j == i) e = cadd(e, g);
        g_M[0][i * NST + j] = e;
        g_MT[0][j * NST + i] = e;
    }
    g_S[0 * NST + i] = Bv;  // s_0 = Bb
}

// ================= squaring + S doubling in one launch =================
__global__ void __launch_bounds__(256, 4) k_sq2(int srcsel, int r) {
    const float2* Min  = g_M[srcsel];
    const float2* MinT = g_MT[srcsel];
    float2* Mout  = g_M[srcsel ^ 1];
    float2* MoutT = g_MT[srcsel ^ 1];
    __shared__ float2 vec[NST];
    __shared__ float2 part[3][NST];
    int blk = blockIdx.x, tid = threadIdx.x;
    int j = tid & 63, q = tid >> 6;
    const float2 zero = make_float2(0.f, 0.f);
    if (blk < 64) {
        if (tid < NST) vec[tid] = Min[blk * NST + tid];
        __syncthreads();
        float2 acc = zero;
#pragma unroll
        for (int nn = 0; nn < 16; nn++) {
            int n = q * 16 + nn;
            acc = cadd(acc, cmul(vec[n], Min[n * NST + j]));
        }
        if (q) part[q - 1][j] = acc;
        __syncthreads();
        if (q == 0) {
            acc = cadd(acc, cadd(part[0][j], cadd(part[1][j], part[2][j])));
            Mout[blk * NST + j] = acc;
            MoutT[j * NST + blk] = acc;
        }
    } else {
        int k = blk - 64;  // k < r
        if (tid < NST) vec[tid] = g_S[k * NST + tid];
        __syncthreads();
        float2 acc = zero;
#pragma unroll
        for (int nn = 0; nn < 16; nn++) {
            int n = q * 16 + nn;
            acc = cadd(acc, cmul(vec[n], MinT[n * NST + j]));
        }
        if (q) part[q - 1][j] = acc;
        __syncthreads();
        if (q == 0) {
            acc = cadd(acc, cadd(part[0][j], cadd(part[1][j], part[2][j])));
            g_S[(k + r) * NST + j] = acc;
        }
    }
}

// ================= K tail: r-chain + cross product (1 block, 1024 thr) =================
#define KT_SMEM_F2 (4160 + 4160 + 1024 + 64 + 64)
__global__ void __launch_bounds__(1024, 1) k_ktail(const float* cre, const float* cim) {
    extern __shared__ float2 sm[];
    float2* ST = sm;
    float2* Ms = ST + 4160;
    float2* Rm = Ms + 4160;
    float2* Rc = Rm + 1024;
    float2* Rn = Rc + 64;
    int tid = threadIdx.x;
    const float2 zero = make_float2(0.f, 0.f);
    for (int e = tid; e < NST * NST; e += 1024) {
        int k = e >> 6, n = e & 63;
        ST[n * 65 + k] = g_S[e];
        Ms[k * 65 + n] = g_M[0][e];
    }
    if (tid < NST) Rc[tid] = make_float2(cre[tid], cim[tid]);
    __syncthreads();
    int i = tid >> 4, q = tid & 15;
    for (int m = 0; m < 16; m++) {
        if (tid < NST) Rm[m * NST + tid] = Rc[tid];
        float2 acc = zero;
#pragma unroll
        for (int nn = 0; nn < 4; nn++) {
            int n = q * 4 + nn;
            acc = cadd(acc, cmul(Rc[n], Ms[n * 65 + i]));
        }
#pragma unroll
        for (int o = 8; o > 0; o >>= 1) {
            acc.x += __shfl_down_sync(0xffffffffu, acc.x, o, 16);
            acc.y += __shfl_down_sync(0xffffffffu, acc.y, o, 16);
        }
        if (q == 0) Rn[i] = acc;
        __syncthreads();
        if (tid < NST) Rc[tid] = Rn[tid];
        __syncthreads();
    }
    int m = tid >> 6, k = tid & 63;
    float acc = 0.f;
#pragma unroll 8
    for (int n = 0; n < NST; n++) {
        float2 a = Rm[m * NST + n];
        float2 s = ST[n * 65 + k];
        acc += a.x * s.x - a.y * s.y;
    }
    g_K[m * NST + k] = acc;
}

// ================= conv on tensor cores (tf32): Toeplitz A-tile =================
// Same 576-block triangular grid & split-buffer outputs as before.
// Smem: Ks float[264] @0 (pad 1088B); Ts unsigned[128*132] @1088; Xs unsigned[2][32*136] @68672.
// Ts pitch 132 -> frag banks 4g+t (perfect); Xs pitch 136 -> frag banks 8t+g (perfect).
#define CONV_SMEM 103488

__global__ void __launch_bounds__(256) k_conv() {
    extern __shared__ char cvs[];
    float* Ks = (float*)cvs;
    unsigned* Ts = (unsigned*)(cvs + 1088);
    unsigned* Xs = (unsigned*)(cvs + 68672);

    int idx = blockIdx.x;
    int b = idx / 144;
    int rem = idx - b * 144;
    int hT = rem / 36;
    int pr = rem - hT * 36;
    int tT = 0;
    while ((tT + 1) * (tT + 2) / 2 <= pr) tT++;
    int sT = pr - tT * (tT + 1) / 2;
    int t0 = tT * 128, s0 = sT * 128, h0 = hT * 128;
    int D0 = t0 - s0;

    int tid = threadIdx.x;
    int lane = tid & 31, warp = tid >> 5;
    int g = lane >> 2, t = lane & 3;
    int wm = warp & 3, wn = warp >> 2;

    // K window into smem (zero-padded => causality for diagonal tiles)
    for (int jj = tid; jj < 264; jj += 256) {
        int d = D0 + jj - 131;
        Ks[jj] = (d >= 0 && d < LSEQ) ? g_K[d] : 0.f;
    }
    __syncthreads();

    // Build Toeplitz tile: Ts[t][s] = tf32(K[D0 + t - s]) = Ks[131 + t - s]
    {
        int tt = tid >> 1, sbase = (tid & 1) * 64;
        const float* kp = Ks + 131 + tt - sbase;
        unsigned* dst = Ts + tt * 132 + sbase;
#pragma unroll
        for (int s = 0; s < 64; s += 4) {
            uint4 v = make_uint4(f2tf(kp[-s]), f2tf(kp[-s - 1]),
                                 f2tf(kp[-s - 2]), f2tf(kp[-s - 3]));
            *(uint4*)(dst + s) = v;
        }
    }

    // Stage + store X chunk 0
    int hq = tid & 31, sr0 = tid >> 5;
    const float* Xg = g_xn + (size_t)(b * LSEQ + s0) * H + h0 + 4 * hq;
    float4 st[4];
#pragma unroll
    for (int i2 = 0; i2 < 4; i2++) st[i2] = *(const float4*)(Xg + (size_t)(sr0 + 8 * i2) * H);
#pragma unroll
    for (int i2 = 0; i2 < 4; i2++) {
        uint4 v = make_uint4(f2tf(st[i2].x), f2tf(st[i2].y), f2tf(st[i2].z), f2tf(st[i2].w));
        *(uint4*)(Xs + (sr0 + 8 * i2) * 136 + 4 * hq) = v;
    }
    __syncthreads();

    float C[2][8][4];
#pragma unroll
    for (int a = 0; a < 2; a++)
#pragma unroll
        for (int nb = 0; nb < 8; nb++)
#pragma unroll
            for (int cc = 0; cc < 4; cc++) C[a][nb][cc] = 0.f;

    for (int ch = 0; ch < 4; ch++) {
        if (ch < 3) {
#pragma unroll
            for (int i2 = 0; i2 < 4; i2++)
                st[i2] = *(const float4*)(Xg + (size_t)((ch + 1) * 32 + sr0 + 8 * i2) * H);
        }
        const unsigned* XB = Xs + (ch & 1) * 4352;
#pragma unroll
        for (int ks = 0; ks < 4; ks++) {
            int kkA = ch * 32 + ks * 8 + t;
            unsigned af[2][4];
#pragma unroll
            for (int mt = 0; mt < 2; mt++) {
                const unsigned* pa = Ts + (wm * 32 + mt * 16 + g) * 132 + kkA;
                af[mt][0] = pa[0];
                af[mt][1] = pa[8 * 132];
                af[mt][2] = pa[4];
                af[mt][3] = pa[8 * 132 + 4];
            }
            const unsigned* pb = XB + (ks * 8 + t) * 136 + wn * 64 + g;
            unsigned bf[8][2];
#pragma unroll
            for (int nt = 0; nt < 8; nt++) {
                bf[nt][0] = pb[nt * 8];
                bf[nt][1] = pb[4 * 136 + nt * 8];
            }
#pragma unroll
            for (int mt = 0; mt < 2; mt++)
#pragma unroll
                for (int nt = 0; nt < 8; nt++)
                    mma_tf32(C[mt][nt], af[mt], bf[nt]);
        }
        if (ch < 3) {
            unsigned* XN = Xs + ((ch + 1) & 1) * 4352;
#pragma unroll
            for (int i2 = 0; i2 < 4; i2++) {
                uint4 v = make_uint4(f2tf(st[i2].x), f2tf(st[i2].y),
                                     f2tf(st[i2].z), f2tf(st[i2].w));
                *(uint4*)(XN + (sr0 + 8 * i2) * 136 + 4 * hq) = v;
            }
        }
        __syncthreads();
    }

    float* P = g_part[sT] + ((size_t)(b * LSEQ) + t0) * H + h0;
#pragma unroll
    for (int mt = 0; mt < 2; mt++) {
        int rr = wm * 32 + mt * 16 + g;
#pragma unroll
        for (int nt = 0; nt < 8; nt++) {
            int cc = wn * 64 + nt * 8 + t * 2;
            *(float2*)(P + (size_t)rr * H + cc)       = make_float2(C[mt][nt][0], C[mt][nt][1]);
            *(float2*)(P + (size_t)(rr + 8) * H + cc) = make_float2(C[mt][nt][2], C[mt][nt][3]);
        }
    }
}

// ================= split reduce + d*xn + GELU =================
__global__ void k_gelu(const float* __restrict__ dscale) {
    int idx = blockIdx.x * 256 + threadIdx.x;
    int row = idx >> 7, c4 = idx & 127;
    int t = row & (LSEQ - 1);
    int tT = t >> 7;
    size_t off = (size_t)row * H + c4 * 4;
    float4 s = make_float4(0.f, 0.f, 0.f, 0.f);
    for (int j = 0; j <= tT; j++) {
        float4 p = *(const float4*)(g_part[j] + off);
        s.x += p.x; s.y += p.y; s.z += p.z; s.w += p.w;
    }
    float dv = dscale[0];
    float4 xn = *(const float4*)(g_xn + off);
    float y0 = s.x + dv * xn.x, y1 = s.y + dv * xn.y;
    float y2 = s.z + dv * xn.z, y3 = s.w + dv * xn.w;
    float4 o;
    float z;
    z = 0.7978845608f * (y0 + 0.044715f * y0 * y0 * y0); o.x = y0 / (1.f + __expf(-2.f * z));
    z = 0.7978845608f * (y1 + 0.044715f * y1 * y1 * y1); o.y = y1 / (1.f + __expf(-2.f * z));
    z = 0.7978845608f * (y2 + 0.044715f * y2 * y2 * y2); o.z = y2 / (1.f + __expf(-2.f * z));
    z = 0.7978845608f * (y3 + 0.044715f * y3 * y3 * y3); o.w = y3 / (1.f + __expf(-2.f * z));
    *(float4*)(g_yg + off) = o;
}

// ================= dual GEMM on tensor cores (tf32 mma.sync) =================
#define GM_SMEM_BYTES (2 * 2 * 4608 * 4)

__global__ void __launch_bounds__(256) k_gemm(
    const float* __restrict__ W1, const float* __restrict__ W2,
    const float* __restrict__ b1, const float* __restrict__ b2,
    const float* __restrict__ skip, float* __restrict__ out) {
    extern __shared__ unsigned sh[];
    int r0 = blockIdx.x * 128, o0 = blockIdx.y * 64;
    int tid = threadIdx.x;
    int lane = tid & 31, warp = tid >> 5;
    int g = lane >> 2, t = lane & 3;
    int wm = warp & 1, wn = warp >> 1;

    int lrow = tid >> 1, lseg = tid & 1;
    const float* Asrc = g_yg + (size_t)(r0 + lrow) * H + lseg * 16;
    int sub = lrow & 15;
    int outn = o0 + (lrow >> 4) * 8 + (sub & 7);
    const float* Bsrc = ((sub < 8) ? W1 : W2) + (size_t)outn * H + lseg * 16;
    unsigned woff = lrow * 36 + lseg * 16;

    float C[4][4][4];
#pragma unroll
    for (int a = 0; a < 4; a++)
#pragma unroll
        for (int b = 0; b < 4; b++)
#pragma unroll
            for (int c = 0; c < 4; c++) C[a][b][c] = 0.f;

#pragma unroll
    for (int q = 0; q < 4; q++) {
        float4 va = *(const float4*)(Asrc + q * 4);
        uint4 ua = make_uint4(f2tf(va.x), f2tf(va.y), f2tf(va.z), f2tf(va.w));
        *(uint4*)&sh[woff + q * 4] = ua;
        float4 vb = *(const float4*)(Bsrc + q * 4);
        uint4 ub = make_uint4(f2tf(vb.x), f2tf(vb.y), f2tf(vb.z), f2tf(vb.w));
        *(uint4*)&sh[4608 + woff + q * 4] = ub;
    }
    __syncthreads();

    for (int ch = 0; ch < 16; ch++) {
        float4 stA[4], stB[4];
        if (ch < 15) {
            const float* pa = Asrc + (ch + 1) * 32;
            const float* pb = Bsrc + (ch + 1) * 32;
#pragma unroll
            for (int q = 0; q < 4; q++) { stA[q] = *(const float4*)(pa + q * 4);
                                          stB[q] = *(const float4*)(pb + q * 4); }
        }
        const unsigned* A = sh + (ch & 1) * 9216;
        const unsigned* B = A + 4608;
#pragma unroll
        for (int ks = 0; ks < 4; ks++) {
            int kk = ks * 8 + t;
            unsigned af[4][4], bf[4][2];
#pragma unroll
            for (int mt = 0; mt < 4; mt++) {
                const unsigned* p = A + (wm * 64 + mt * 16 + g) * 36 + kk;
                af[mt][0] = p[0]; af[mt][1] = p[8 * 36];
                af[mt][2] = p[4]; af[mt][3] = p[8 * 36 + 4];
            }
#pragma unroll
            for (int nt = 0; nt < 4; nt++) {
                const unsigned* p = B + (wn * 32 + nt * 8 + g) * 36 + kk;
                bf[nt][0] = p[0]; bf[nt][1] = p[4];
            }
#pragma unroll
            for (int mt = 0; mt < 4; mt++)
#pragma unroll
                for (int nt = 0; nt < 4; nt++)
                    mma_tf32(C[mt][nt], af[mt], bf[nt]);
        }
        if (ch < 15) {
            unsigned* dA = sh + ((ch + 1) & 1) * 9216 + woff;
            unsigned* dB = dA + 4608;
#pragma unroll
            for (int q = 0; q < 4; q++) {
                *(uint4*)(dA + q * 4) = make_uint4(f2tf(stA[q].x), f2tf(stA[q].y),
                                                   f2tf(stA[q].z), f2tf(stA[q].w));
                *(uint4*)(dB + q * 4) = make_uint4(f2tf(stB[q].x), f2tf(stB[q].y),
                                                   f2tf(stB[q].z), f2tf(stB[q].w));
            }
        }
        __syncthreads();
    }

    float b1v[2][2], b2v[2][2];
#pragma unroll
    for (int p = 0; p < 2; p++) {
        int col = o0 + wn * 16 + p * 8 + t * 2;
        b1v[p][0] = b1[col]; b1v[p][1] = b1[col + 1];
        b2v[p][0] = b2[col]; b2v[p][1] = b2[col + 1];
    }
#pragma unroll
    for (int mt = 0; mt < 4; mt++) {
        int row = r0 + wm * 64 + mt * 16 + g;
#pragma unroll
        for (int p = 0; p < 2; p++) {
            int col = o0 + wn * 16 + p * 8 + t * 2;
            const float* pr = C[mt][2 * p];
            const float* ga = C[mt][2 * p + 1];
#pragma unroll
            for (int h = 0; h < 2; h++) {
                int rw = row + h * 8;
                float v0 = pr[h * 2 + 0] + b1v[p][0];
                float v1 = pr[h * 2 + 1] + b1v[p][1];
                float g0 = ga[h * 2 + 0] + b2v[p][0];
                float g1 = ga[h * 2 + 1] + b2v[p][1];
                float o0v = skip[(size_t)rw * H + col]     + v0 / (1.f + __expf(-g0));
                float o1v = skip[(size_t)rw * H + col + 1] + v1 / (1.f + __expf(-g1));
                *(float2*)(out + (size_t)rw * H + col) = make_float2(o0v, o1v);
            }
        }
    }
}

extern "C" void kernel_launch(void* const* d_in, const int* in_sizes, int n_in,
                              void* d_out, int out_size) {
    const float* x   = (const float*)d_in[0];
    const float* nw  = (const float*)d_in[1];
    const float* nb  = (const float*)d_in[2];
    const float* lre = (const float*)d_in[3];
    const float* lim = (const float*)d_in[4];
    const float* pre = (const float*)d_in[5];
    const float* pim = (const float*)d_in[6];
    const float* bre = (const float*)d_in[7];
    const float* bim = (const float*)d_in[8];
    const float* cre = (const float*)d_in[9];
    const float* cim = (const float*)d_in[10];
    const float* dd  = (const float*)d_in[11];
    const float* ls  = (const float*)d_in[12];
    const float* W1  = (const float*)d_in[13];
    const float* b1  = (const float*)d_in[14];
    const float* W2  = (const float*)d_in[15];
    const float* b2  = (const float*)d_in[16];
    float* out = (float*)d_out;

    size_t kt_smem = (size_t)KT_SMEM_F2 * sizeof(float2);
    cudaFuncSetAttribute(k_ktail, cudaFuncAttributeMaxDynamicSharedMemorySize, (int)kt_smem);
    cudaFuncSetAttribute(k_gemm, cudaFuncAttributeMaxDynamicSharedMemorySize, GM_SMEM_BYTES);
    cudaFuncSetAttribute(k_conv, cudaFuncAttributeMaxDynamicSharedMemorySize, CONV_SMEM);

    k_ln<<<NROWS, 128>>>(x, nw, nb);
    k_setup<<<1, 64>>>(lre, lim, pre, pim, bre, bim, ls);
    for (int j = 0; j < 6; j++)
        k_sq2<<<64 + (1 << j), 256>>>(j & 1, 1 << j);
    k_ktail<<<1, 1024, kt_smem>>>(cre, cim);
    k_conv<<<576, 256, CONV_SMEM>>>();
    k_gelu<<<2048, 256>>>(dd);
    k_gemm<<<dim3(32, 8), 256, GM_SMEM_BYTES>>>(W1, W2, b1, b2, x, out);
}